// round 10
// baseline (speedup 1.0000x reference)
#include <cuda_runtime.h>
#include <stdint.h>

#define BATCH   4
#define NPTS    100000
#define TOTAL   (BATCH * NPTS)
#define D_IN    16
#define D_TOT   19
#define MLP_N   128
#define GRID_X  468
#define GRID_Y  468
#define VOL     (GRID_X * GRID_Y)
#define NVOX    (BATCH * VOL)        // 876096 = 27378 * 32
#define CAP     16

#define THREADS 256
#define BLOCKS  740                  // persistent: 5 blocks/SM * 148
#define NWARPS  (BLOCKS * THREADS / 32)
#define STRIDE  (NWARPS * 32)

#define VOX_BYTES (MLP_N * 4)        // 512 B per voxel
#define ZBUF_BYTES (32 * VOX_BYTES)  // 16 KB: one full chunk of zeros

__device__ int d_cnt[NVOX];                 // per-voxel point count (self-zeroing)
__device__ int d_pidx[(size_t)NVOX * CAP];  // per-voxel point indices

// ---- packed f32x2 helpers (FFMA2, PTX-only) ----
__device__ __forceinline__ unsigned long long dup2(float v) {
    unsigned long long r;
    asm("mov.b64 %0, {%1, %1};" : "=l"(r) : "f"(v));
    return r;
}
__device__ __forceinline__ unsigned long long fma2(unsigned long long a,
                                                   unsigned long long b,
                                                   unsigned long long c) {
    unsigned long long d;
    asm("fma.rn.f32x2 %0, %1, %2, %3;" : "=l"(d) : "l"(a), "l"(b), "l"(c));
    return d;
}
__device__ __forceinline__ void unpack2(unsigned long long p, float& lo, float& hi) {
    asm("mov.b64 {%0, %1}, %2;" : "=f"(lo), "=f"(hi) : "l"(p));
}
__device__ __forceinline__ unsigned long long pack2(float lo, float hi) {
    unsigned long long r;
    asm("mov.b64 %0, {%1, %2};" : "=l"(r) : "f"(lo), "f"(hi));
    return r;
}
__device__ __forceinline__ void prefetchL1(const void* ptr) {
    asm volatile("prefetch.global.L1 [%0];" :: "l"(ptr));
}
__device__ __forceinline__ uint32_t smem_u32(const void* p) {
    uint32_t a;
    asm("{ .reg .u64 t; cvta.to.shared.u64 t, %1; cvt.u32.u64 %0, t; }"
        : "=r"(a) : "l"(p));
    return a;
}
// async-proxy bulk store: SMEM -> GMEM, bypasses the LSU store-wavefront path
__device__ __forceinline__ void bulk_store(void* gptr, uint32_t saddr, uint32_t bytes) {
    asm volatile("cp.async.bulk.global.shared::cta.bulk_group [%0], [%1], %2;"
                 :: "l"(gptr), "r"(saddr), "r"(bytes) : "memory");
}

// ---- K2: bin valid points (no single-address counters) ----
__global__ void __launch_bounds__(256)
bin_points_kernel(const float* __restrict__ xyz,
                  const unsigned int* __restrict__ mask)
{
    const int p = blockIdx.x * blockDim.x + threadIdx.x;
    if (p >= TOTAL) return;
    if (mask[p] == 0u) return;

    const float x = xyz[p * 3 + 0];
    const float y = xyz[p * 3 + 1];
    const float z = xyz[p * 3 + 2];
    const int ivx = (int)floorf(x / 0.32f) + 234;
    const int ivy = (int)floorf(y / 0.32f) + 234;
    const int ivz = (int)floorf(z / 6.0f) + 1;
    if (ivx < 0 || ivx >= GRID_X || ivy < 0 || ivy >= GRID_Y || ivz != 0) return;

    const int batch = p / NPTS;
    const int vid = batch * VOL + ivx * GRID_X + ivy;
    const int slot = atomicAdd(&d_cnt[vid], 1);
    if (slot < CAP) d_pidx[(size_t)vid * CAP + slot] = p;
}

// ---- K3: fused gather; empties via async bulk zero-stores; self-zeroes d_cnt ----
__global__ void __launch_bounds__(THREADS, 5)
gather_kernel(const float* __restrict__ xyz,
              const float* __restrict__ pfeat,
              const float* __restrict__ W,
              const float* __restrict__ bias,
              float* __restrict__ out)
{
    __shared__ float4 sW4[D_TOT * (MLP_N / 4)];       // 9728 B (packed f32x2 pairs)
    __shared__ __align__(16) float zbuf[ZBUF_BYTES / 4]; // 16 KB of zeros

    for (int i = threadIdx.x; i < D_TOT * (MLP_N / 4); i += THREADS)
        sW4[i] = ((const float4*)W)[i];
    {
        const float4 z4 = make_float4(0.f, 0.f, 0.f, 0.f);
        for (int i = threadIdx.x; i < ZBUF_BYTES / 16; i += THREADS)
            ((float4*)zbuf)[i] = z4;
    }
    __syncthreads();
    asm volatile("fence.proxy.async.shared::cta;" ::: "memory"); // STS -> async proxy
    const uint32_t zaddr = smem_u32(zbuf);

    const int lane  = threadIdx.x & 31;
    const int gwarp = (blockIdx.x * THREADS + threadIdx.x) >> 5;

    const float4 b4 = __ldg(((const float4*)bias) + lane);
    const unsigned long long b01 = pack2(b4.x, b4.y);
    const unsigned long long b23 = pack2(b4.z, b4.w);

    int chunk = gwarp * 32;

    // Pipeline: counts 2 chunks deep, first-pidx 1 chunk deep (lane-parallel).
    int c = 0, c1 = 0, p = 0;
    if (chunk < NVOX) {
        c = __ldg(&d_cnt[chunk + lane]);
        p = (c > 0) ? __ldg(&d_pidx[(size_t)(chunk + lane) * CAP]) : 0;
        if (c > 0) {
            prefetchL1(xyz + (size_t)p * 3);
            prefetchL1(pfeat + (size_t)p * D_IN);
        }
    }
    if (chunk + STRIDE < NVOX) c1 = __ldg(&d_cnt[chunk + STRIDE + lane]);

    for (; chunk < NVOX; chunk += STRIDE) {
        const int nxt  = chunk + STRIDE;
        const int nxt2 = chunk + 2 * STRIDE;
        const int c2 = (nxt2 < NVOX) ? __ldg(&d_cnt[nxt2 + lane]) : 0;
        int p1 = 0;
        if (nxt < NVOX && c1 > 0)
            p1 = __ldg(&d_pidx[(size_t)(nxt + lane) * CAP]);

        d_cnt[chunk + lane] = 0;   // reset for next replay (exclusive owner)

        const unsigned em = __ballot_sync(0xffffffffu, c == 0);  // empty-voxel mask

        // ---- empty runs -> async bulk zero-stores (off the LSU path) ----
        // lane is a run-start if empty(lane) && !empty(lane-1)
        const unsigned starts = em & ~((em << 1) | 0u);
        if ((starts >> lane) & 1u) {
            const unsigned rest = (~em) >> lane;           // bits above lane: occupied
            const int len = rest ? (__ffs(rest) - 1) : (32 - lane);
            bulk_store(out + (size_t)(chunk + lane) * MLP_N, zaddr,
                       (uint32_t)len * VOX_BYTES);
        }

        // ---- occupied voxels ----
        unsigned om = ~em;
        while (om) {
            const int i = __ffs(om) - 1;
            om &= om - 1;
            const int ci = __shfl_sync(0xffffffffu, c, i);
            const int v  = chunk + i;
            const int npt = ci < CAP ? ci : CAP;
            unsigned long long vmax01 = pack2(-1e30f, -1e30f);
            unsigned long long vmax23 = vmax01;

            for (int k = 0; k < npt; ++k) {
                const int pt = (k == 0) ? __shfl_sync(0xffffffffu, p, i)
                                        : __ldg(&d_pidx[(size_t)v * CAP + k]);
                const float x = xyz[pt * 3 + 0];
                const float y = xyz[pt * 3 + 1];
                const float z = xyz[pt * 3 + 2];
                const float dx = x - floorf(x / 0.32f) * 0.32f;
                const float dy = y - floorf(y / 0.32f) * 0.32f;
                const float dz = z - floorf(z / 6.0f) * 6.0f;

                const float4* f4 = (const float4*)(pfeat + (size_t)pt * D_IN);
                const float4 fa = f4[0], fb = f4[1], fc = f4[2], fd = f4[3];
                const float vin[D_TOT] = {
                    fa.x, fa.y, fa.z, fa.w,
                    fb.x, fb.y, fb.z, fb.w,
                    fc.x, fc.y, fc.z, fc.w,
                    fd.x, fd.y, fd.z, fd.w,
                    dx, dy, dz
                };
                unsigned long long acc01 = b01, acc23 = b23;
                #pragma unroll
                for (int d = 0; d < D_TOT; ++d) {
                    const ulonglong2 wp =
                        *(const ulonglong2*)(sW4 + d * (MLP_N / 4) + lane);
                    const unsigned long long vv = dup2(vin[d]);
                    acc01 = fma2(vv, wp.x, acc01);
                    acc23 = fma2(vv, wp.y, acc23);
                }
                float a0, a1, a2, a3, m0, m1, m2, m3;
                unpack2(acc01, a0, a1); unpack2(acc23, a2, a3);
                unpack2(vmax01, m0, m1); unpack2(vmax23, m2, m3);
                vmax01 = pack2(fmaxf(m0, a0), fmaxf(m1, a1));
                vmax23 = pack2(fmaxf(m2, a2), fmaxf(m3, a3));
            }

            float m0, m1, m2, m3;
            unpack2(vmax01, m0, m1);
            unpack2(vmax23, m2, m3);
            // relu monotone: max-then-relu == max-of-relus
            __stcs(((float4*)(out + (size_t)v * MLP_N)) + lane,
                   make_float4(fmaxf(m0, 0.f), fmaxf(m1, 0.f),
                               fmaxf(m2, 0.f), fmaxf(m3, 0.f)));
        }

        if (c1 > 0) {   // p1 landed by now: warm L1 for next chunk's first points
            prefetchL1(xyz + (size_t)p1 * 3);
            prefetchL1(pfeat + (size_t)p1 * D_IN);
        }
        c = c1; c1 = c2; p = p1;
    }

    // Drain this thread's bulk-store group before smem (zbuf) is torn down.
    asm volatile("cp.async.bulk.commit_group;");
    asm volatile("cp.async.bulk.wait_group 0;" ::: "memory");
}

extern "C" void kernel_launch(void* const* d_in, const int* in_sizes, int n_in,
                              void* d_out, int out_size)
{
    const float*        xyz   = (const float*)d_in[0];
    const float*        pfeat = (const float*)d_in[1];
    const unsigned int* mask  = (const unsigned int*)d_in[2];
    const float*        W     = (const float*)d_in[3];
    const float*        bias  = (const float*)d_in[4];
    float*              out   = (float*)d_out;

    // d_cnt starts zeroed (static init) and is re-zeroed by gather_kernel each call.
    bin_points_kernel<<<(TOTAL + 255) / 256, 256>>>(xyz, mask);
    gather_kernel<<<BLOCKS, THREADS>>>(xyz, pfeat, W, bias, out);
}